// round 5
// baseline (speedup 1.0000x reference)
#include <cuda_runtime.h>
#include <cstdint>

#define T_STEPS 1024
#define B_SZ    32
#define I_SZ    512
#define H_SZ    512
#define G4      2048                 // 4*H
#define TBH     (T_STEPS * B_SZ * H_SZ)
#define BH      (B_SZ * H_SZ)
#define NSET    4                    // CTA sets (8 batches each)
#define NC      32                   // CTAs per set
#define VB      4                    // batches per virtual group (2 vgroups/set)
#define WPITCH  516                  // padded smem row pitch (floats)

typedef unsigned long long ull;

// ---------------- device scratch (no allocation allowed) ----------------
__device__ float g_gates[(size_t)T_STEPS * B_SZ * G4];   // [t][b][p], p = 4j+g
__device__ float g_wih_p[G4 * I_SZ];                     // packed W_ih (p = 4j+g)
__device__ float g_whh_p[G4 * H_SZ];                     // packed W_hh (p = 4j+g)
__device__ float g_bias_p[G4];                           // b_ih + b_hh, packed
__device__ float g_hbuf[NSET * 2 * 2 * VB * H_SZ];       // [set][vg][ph][b4][j]
__device__ unsigned g_cnt[8 * 32];                       // per-vgroup arrival counter (padded)
__device__ unsigned g_gen2[8 * 32];                      // per-vgroup generation (padded)

// ---------------- packed f32x2 helpers ----------------
__device__ __forceinline__ void ffma2(ull &d, ull a, ull b) {
    asm("fma.rn.f32x2 %0, %1, %2, %3;" : "=l"(d) : "l"(a), "l"(b), "l"(d));
}
__device__ __forceinline__ void fadd2(ull &d, ull a) {
    asm("add.rn.f32x2 %0, %1, %2;" : "=l"(d) : "l"(d), "l"(a));
}
__device__ __forceinline__ ull pack2(float x) {
    ull r; asm("mov.b64 %0, {%1, %1};" : "=l"(r) : "f"(x)); return r;
}
__device__ __forceinline__ float2 unpack2(ull v) {
    float2 r; asm("mov.b64 {%0, %1}, %2;" : "=f"(r.x), "=f"(r.y) : "l"(v)); return r;
}
__device__ __forceinline__ unsigned ld_acq(const unsigned* p) {
    unsigned v; asm volatile("ld.acquire.gpu.global.u32 %0, [%1];" : "=r"(v) : "l"(p) : "memory");
    return v;
}
__device__ __forceinline__ void st_rel(unsigned* p, unsigned v) {
    asm volatile("st.release.gpu.global.u32 [%0], %1;" :: "l"(p), "r"(v) : "memory");
}

__device__ __forceinline__ float sigf(float x) {
    return __fdividef(1.f, 1.f + __expf(-x));
}
__device__ __forceinline__ float tanh_fast(float x) {
    float ax = fabsf(x);
    float e  = __expf(-2.f * ax);
    float r  = __fdividef(1.f - e, 1.f + e);
    return copysignf(r, x);
}

// ---------------- prep: pack weights, scatter h0, reset sync words ----------------
__global__ void prep_kernel(const float* __restrict__ Wih, const float* __restrict__ Whh,
                            const float* __restrict__ bih, const float* __restrict__ bhh,
                            const float* __restrict__ h0) {
    int p = blockIdx.x;                     // packed row p = 4j + g
    int g = p & 3, j = p >> 2;
    int orig = g * H_SZ + j;

    const float* srcI = Wih + (size_t)orig * I_SZ;
    const float* srcH = Whh + (size_t)orig * H_SZ;
    float* dI = g_wih_p + (size_t)p * I_SZ;
    float* dH = g_whh_p + (size_t)p * H_SZ;
    for (int k = threadIdx.x; k < I_SZ; k += blockDim.x) dI[k] = srcI[k];
    for (int k = threadIdx.x; k < H_SZ; k += blockDim.x) dH[k] = srcH[k];
    if (threadIdx.x == 0) g_bias_p[p] = bih[orig] + bhh[orig];

    if (p < H_SZ) {                          // h0 -> g_hbuf[set][vg][0][b&3][j=p]
        for (int b = threadIdx.x; b < B_SZ; b += blockDim.x) {
            int set = b >> 3, vg = (b >> 2) & 1, b4 = b & 3;
            g_hbuf[(((size_t)(set * 2 + vg) * 2 + 0) * VB + b4) * H_SZ + p] =
                h0[(size_t)b * H_SZ + p];
        }
    }
    if (p < 8 && threadIdx.x == 0) { g_cnt[p * 32] = 0; g_gen2[p * 32] = 0; }
}

// ---------------- phase 1: gates_x GEMM  C[m][p] = A[m][:] . Wp[p][:] + bias[p] ----------------
#define BM 128
#define BN 64
#define BK 16
#define LDA (BM + 4)
#define LDB (BN + 4)

__global__ __launch_bounds__(256) void gemm_x_kernel(const float* __restrict__ A) {
    __shared__ float sA[BK][LDA];
    __shared__ float sB[BK][LDB];
    int tid   = threadIdx.x;
    int mBase = blockIdx.y * BM;
    int nBase = blockIdx.x * BN;
    int tm = tid & 15, tn = tid >> 4;

    int aM0 = tid >> 2;
    int aK0 = (tid & 3) * 4;
    int bN  = tid >> 2;
    int bK  = (tid & 3) * 4;

    const float* Ag = A + (size_t)mBase * I_SZ;
    const float* Bg = g_wih_p + (size_t)nBase * I_SZ;

    float4 ra0 = *(const float4*)(Ag + (size_t)aM0 * I_SZ + aK0);
    float4 ra1 = *(const float4*)(Ag + (size_t)(aM0 + 64) * I_SZ + aK0);
    float4 rb  = *(const float4*)(Bg + (size_t)bN * I_SZ + bK);

    ull acc[4][4];
#pragma unroll
    for (int u = 0; u < 4; u++)
#pragma unroll
        for (int j = 0; j < 4; j++) acc[u][j] = 0ull;

    const int KT = I_SZ / BK;
    for (int kt = 0; kt < KT; kt++) {
        sA[aK0 + 0][aM0] = ra0.x; sA[aK0 + 1][aM0] = ra0.y;
        sA[aK0 + 2][aM0] = ra0.z; sA[aK0 + 3][aM0] = ra0.w;
        sA[aK0 + 0][aM0 + 64] = ra1.x; sA[aK0 + 1][aM0 + 64] = ra1.y;
        sA[aK0 + 2][aM0 + 64] = ra1.z; sA[aK0 + 3][aM0 + 64] = ra1.w;
        sB[bK + 0][bN] = rb.x; sB[bK + 1][bN] = rb.y;
        sB[bK + 2][bN] = rb.z; sB[bK + 3][bN] = rb.w;
        __syncthreads();

        if (kt + 1 < KT) {
            int k0 = (kt + 1) * BK;
            ra0 = *(const float4*)(Ag + (size_t)aM0 * I_SZ + k0 + aK0);
            ra1 = *(const float4*)(Ag + (size_t)(aM0 + 64) * I_SZ + k0 + aK0);
            rb  = *(const float4*)(Bg + (size_t)bN * I_SZ + k0 + bK);
        }

#pragma unroll
        for (int kk = 0; kk < BK; kk++) {
            ulonglong2 a01 = *(const ulonglong2*)&sA[kk][tm * 8];
            ulonglong2 a23 = *(const ulonglong2*)&sA[kk][tm * 8 + 4];
            float4 b4 = *(const float4*)&sB[kk][tn * 4];
            ull b0 = pack2(b4.x), b1 = pack2(b4.y), b2 = pack2(b4.z), b3 = pack2(b4.w);
            ffma2(acc[0][0], a01.x, b0); ffma2(acc[0][1], a01.x, b1);
            ffma2(acc[0][2], a01.x, b2); ffma2(acc[0][3], a01.x, b3);
            ffma2(acc[1][0], a01.y, b0); ffma2(acc[1][1], a01.y, b1);
            ffma2(acc[1][2], a01.y, b2); ffma2(acc[1][3], a01.y, b3);
            ffma2(acc[2][0], a23.x, b0); ffma2(acc[2][1], a23.x, b1);
            ffma2(acc[2][2], a23.x, b2); ffma2(acc[2][3], a23.x, b3);
            ffma2(acc[3][0], a23.y, b0); ffma2(acc[3][1], a23.y, b1);
            ffma2(acc[3][2], a23.y, b2); ffma2(acc[3][3], a23.y, b3);
        }
        __syncthreads();
    }

    float4 bias = *(const float4*)&g_bias_p[nBase + tn * 4];
    float* C = g_gates + (size_t)(mBase + tm * 8) * G4 + nBase + tn * 4;
#pragma unroll
    for (int u = 0; u < 4; u++) {
        float2 c0 = unpack2(acc[u][0]);
        float2 c1 = unpack2(acc[u][1]);
        float2 c2 = unpack2(acc[u][2]);
        float2 c3 = unpack2(acc[u][3]);
        float4 lo = {c0.x + bias.x, c1.x + bias.y, c2.x + bias.z, c3.x + bias.w};
        float4 hi = {c0.y + bias.x, c1.y + bias.y, c2.y + bias.z, c3.y + bias.w};
        *(float4*)(C + (size_t)(2 * u) * G4)     = lo;
        *(float4*)(C + (size_t)(2 * u + 1) * G4) = hi;
    }
}

// ---------------- phase 2: persistent scan, 2 pipelined vgroups per CTA set ----------------
// 4 sets x 32 CTAs. Set s owns batches [8s, 8s+8), split into vgroup X = [8s,8s+4)
// and Y = [8s+4,8s+8). Phases alternate X,Y: the publish->visibility latency of one
// vgroup hides under the other vgroup's compute. CTA c owns packed rows [64c,64c+64).
// Compute: lane = (r = lane>>2, b = lane&3); thread owns row (wid*8+r) x batch b, full K.
__global__ __launch_bounds__(256) void scan_kernel(const float* __restrict__ c0,
                                                   float* __restrict__ out, int out_size) {
    extern __shared__ float smem[];
    float* sh_w = smem;                 // 64 x WPITCH
    float* sh_h = smem + 64 * WPITCH;   // VB x WPITCH (staging, reused per phase)

    int tid  = threadIdx.x;
    int set  = blockIdx.x >> 5;
    int c    = blockIdx.x & 31;
    int lane = tid & 31, wid = tid >> 5;
    int r    = lane >> 2;               // 0..7
    int bl   = lane & 3;                // 0..3

    // W_hh slice -> padded SMEM (resident all 1024 steps)
    {
        const float4* wsrc = (const float4*)(g_whh_p + (size_t)c * 64 * H_SZ);
#pragma unroll
        for (int i = 0; i < 32; i++) {
            int gi = tid + i * 256;          // float4 index 0..8191
            int rr = gi >> 7, k4 = gi & 127;
            *(float4*)(sh_w + rr * WPITCH + k4 * 4) = __ldg(wsrc + gi);
        }
    }

    // per-vgroup pointers/state
    float*    hb[2];
    unsigned* cnt[2];
    unsigned* gen[2];
#pragma unroll
    for (int v = 0; v < 2; v++) {
        hb[v]  = g_hbuf + (size_t)(set * 2 + v) * 2 * VB * H_SZ;
        cnt[v] = g_cnt  + (set * 2 + v) * 32;
        gen[v] = g_gen2 + (set * 2 + v) * 32;
    }

    // epilogue role: lanes 0..7 per warp own output (jl = 2*wid + (lane>>2), b = lane&3)
    bool epi = (lane < 8);
    int  eb  = lane & 3;
    int  sel = lane >> 2;
    int  ejl = 2 * wid + sel;
    int  ej  = c * 16 + ejl;
    float cv[2];
    const float4* gxp[2];
    int bg[2];
#pragma unroll
    for (int v = 0; v < 2; v++) {
        bg[v] = set * 8 + v * VB + eb;
        cv[v] = 0.f;
        gxp[v] = (const float4*)g_gates;
        if (epi) {
            cv[v]  = c0[(size_t)bg[v] * H_SZ + ej];
            gxp[v] = (const float4*)(g_gates + (size_t)bg[v] * G4 + c * 64 + ejl * 4);
        }
    }
    __syncthreads();

    const float* wr   = sh_w + (wid * 8 + r) * WPITCH;
    const float* hrow = sh_h + bl * WPITCH;

    for (int t = 0; t < T_STEPS; t++) {
        // prefetch gates_x for both phases (DRAM latency hidden by phase work)
        float4 gxv[2];
        if (epi) {
            gxv[0] = __ldg(gxp[0] + (size_t)t * (B_SZ * G4 / 4));
            gxv[1] = __ldg(gxp[1] + (size_t)t * (B_SZ * G4 / 4));
        }

#pragma unroll
        for (int v = 0; v < 2; v++) {
            // wait for h[t] of this vgroup (fast path: published one phase ago)
            if (tid == 0) {
                while (ld_acq(gen[v]) < (unsigned)t) {}
            }
            __syncthreads();

            // stage h[t] (VB*H_SZ = 2048 floats = 512 float4)
            {
                const float4* hsrc = (const float4*)(hb[v] + (t & 1) * (VB * H_SZ));
#pragma unroll
                for (int i = 0; i < 2; i++) {
                    int gi = tid + i * 256;
                    int hbk = gi >> 7, k4 = gi & 127;
                    *(float4*)(sh_h + hbk * WPITCH + k4 * 4) = __ldcg(hsrc + gi);
                }
            }
            __syncthreads();

            // dot: row (wid*8+r) x batch bl over K=512
            ull a0 = 0, a1 = 0, a2 = 0, a3 = 0;
#pragma unroll 8
            for (int k = 0; k < H_SZ; k += 8) {
                ulonglong2 h0v = *(const ulonglong2*)(hrow + k);
                ulonglong2 w0v = *(const ulonglong2*)(wr + k);
                ulonglong2 h1v = *(const ulonglong2*)(hrow + k + 4);
                ulonglong2 w1v = *(const ulonglong2*)(wr + k + 4);
                ffma2(a0, h0v.x, w0v.x); ffma2(a1, h0v.y, w0v.y);
                ffma2(a2, h1v.x, w1v.x); ffma2(a3, h1v.y, w1v.y);
            }
            fadd2(a0, a1); fadd2(a2, a3); fadd2(a0, a2);
            float2 sf = unpack2(a0);
            float s = sf.x + sf.y;

            // gather 4 gates of (ejl, eb): source lane = 16*sel + 4*g + b
            int sb = 16 * (lane >> 2) + (lane & 3);
            float q0 = __shfl_sync(0xffffffffu, s, sb);
            float q1 = __shfl_sync(0xffffffffu, s, sb + 4);
            float q2 = __shfl_sync(0xffffffffu, s, sb + 8);
            float q3 = __shfl_sync(0xffffffffu, s, sb + 12);

            float hn = 0.f;
            if (epi) {
                float pi = q0 + gxv[v].x;
                float pf = q1 + gxv[v].y;
                float pg = q2 + gxv[v].z;
                float po = q3 + gxv[v].w;
                float ig = sigf(pi), fg = sigf(pf), og = sigf(po);
                float gg = tanh_fast(pg);
                cv[v] = fg * cv[v] + ig * gg;
                hn = og * tanh_fast(cv[v]);
                hb[v][((t + 1) & 1) * (VB * H_SZ) + eb * H_SZ + ej] = hn;
            }
            __syncthreads();                  // h stores + smem reads complete

            // publish (tid0) while others proceed to out-store / next-phase wait
            if (tid == 0) {
                __threadfence();
                unsigned old = atomicAdd(cnt[v], 1u);
                if (old == (unsigned)(t + 1) * NC - 1u)
                    st_rel(gen[v], (unsigned)(t + 1));
            }
            if (epi) {
                out[(size_t)t * BH + (size_t)bg[v] * H_SZ + ej] = hn;
                if (t == T_STEPS - 1 && out_size >= TBH + 2 * BH) {
                    out[TBH + bg[v] * H_SZ + ej]      = hn;      // h_f
                    out[TBH + BH + bg[v] * H_SZ + ej] = cv[v];   // c_f
                }
            }
        }
    }
}

// ---------------- launch ----------------
extern "C" void kernel_launch(void* const* d_in, const int* in_sizes, int n_in,
                              void* d_out, int out_size) {
    const float* input = (const float*)d_in[0];
    const float* h0    = (const float*)d_in[1];
    const float* c0    = (const float*)d_in[2];
    const float* Wih   = (const float*)d_in[3];
    const float* Whh   = (const float*)d_in[4];
    const float* bih   = (const float*)d_in[5];
    const float* bhh   = (const float*)d_in[6];
    float* out = (float*)d_out;

    prep_kernel<<<G4, 128>>>(Wih, Whh, bih, bhh, h0);

    dim3 grid(G4 / BN, (T_STEPS * B_SZ) / BM);
    gemm_x_kernel<<<grid, 256>>>(input);

    const int scan_smem = (64 + VB) * WPITCH * (int)sizeof(float);  // 140352 B
    cudaFuncSetAttribute(scan_kernel, cudaFuncAttributeMaxDynamicSharedMemorySize, scan_smem);
    scan_kernel<<<NSET * NC, 256, scan_smem>>>(c0, out, out_size);
}

// round 6
// speedup vs baseline: 1.0866x; 1.0866x over previous
#include <cuda_runtime.h>
#include <cstdint>

#define T_STEPS 1024
#define B_SZ    32
#define I_SZ    512
#define H_SZ    512
#define G4      2048                 // 4*H
#define TBH     (T_STEPS * B_SZ * H_SZ)
#define BH      (B_SZ * H_SZ)
#define NG      4                    // independent batch groups (8 batches each)
#define NC      32                   // CTAs per group
#define WPITCH  516                  // padded smem row pitch (floats)

typedef unsigned long long ull;

// ---------------- device scratch (no allocation allowed) ----------------
__device__ float g_gates[(size_t)T_STEPS * B_SZ * G4];   // [t][b][p], p = 4j+g
__device__ float g_wih_p[G4 * I_SZ];                     // packed W_ih (p = 4j+g)
__device__ float g_whh_p[G4 * H_SZ];                     // packed W_hh (p = 4j+g)
__device__ float g_bias_p[G4];                           // b_ih + b_hh, packed
__device__ ull   g_hpk[NG * 2 * 8 * H_SZ];               // [grp][ph][b8][j] : (tag<<32)|h

// ---------------- packed f32x2 helpers ----------------
__device__ __forceinline__ void ffma2(ull &d, ull a, ull b) {
    asm("fma.rn.f32x2 %0, %1, %2, %3;" : "=l"(d) : "l"(a), "l"(b), "l"(d));
}
__device__ __forceinline__ void fadd2(ull &d, ull a) {
    asm("add.rn.f32x2 %0, %1, %2;" : "=l"(d) : "l"(d), "l"(a));
}
__device__ __forceinline__ ull pack2(float x) {
    ull r; asm("mov.b64 %0, {%1, %1};" : "=l"(r) : "f"(x)); return r;
}
__device__ __forceinline__ float2 unpack2(ull v) {
    float2 r; asm("mov.b64 {%0, %1}, %2;" : "=f"(r.x), "=f"(r.y) : "l"(v)); return r;
}
__device__ __forceinline__ ull ld_acq64(const ull* p) {
    ull v; asm volatile("ld.acquire.gpu.global.u64 %0, [%1];" : "=l"(v) : "l"(p) : "memory");
    return v;
}
__device__ __forceinline__ void st_rel64(ull* p, ull v) {
    asm volatile("st.release.gpu.global.u64 [%0], %1;" :: "l"(p), "l"(v) : "memory");
}

__device__ __forceinline__ float sigf(float x) {
    return __fdividef(1.f, 1.f + __expf(-x));
}
__device__ __forceinline__ float tanh_fast(float x) {
    float ax = fabsf(x);
    float e  = __expf(-2.f * ax);
    float r  = __fdividef(1.f - e, 1.f + e);
    return copysignf(r, x);
}

// ---------------- prep: pack weights, init tagged h buffers ----------------
__global__ void prep_kernel(const float* __restrict__ Wih, const float* __restrict__ Whh,
                            const float* __restrict__ bih, const float* __restrict__ bhh,
                            const float* __restrict__ h0) {
    int p = blockIdx.x;                     // packed row p = 4j + g
    int g = p & 3, j = p >> 2;
    int orig = g * H_SZ + j;

    const float* srcI = Wih + (size_t)orig * I_SZ;
    const float* srcH = Whh + (size_t)orig * H_SZ;
    float* dI = g_wih_p + (size_t)p * I_SZ;
    float* dH = g_whh_p + (size_t)p * H_SZ;
    for (int k = threadIdx.x; k < I_SZ; k += blockDim.x) dI[k] = srcI[k];
    for (int k = threadIdx.x; k < H_SZ; k += blockDim.x) dH[k] = srcH[k];
    if (threadIdx.x == 0) g_bias_p[p] = bih[orig] + bhh[orig];

    // tagged h init: phase0 = (tag 0, h0), phase1 = (tag ~0, junk)  [MUST reset per launch]
    if (p < H_SZ) {
        for (int b = threadIdx.x; b < B_SZ; b += blockDim.x) {
            int grp = b >> 3, b8 = b & 7;
            ull* base = g_hpk + (size_t)grp * 2 * 8 * H_SZ;
            base[b8 * H_SZ + p] = (ull)__float_as_uint(h0[(size_t)b * H_SZ + p]);  // tag 0
            base[8 * H_SZ + b8 * H_SZ + p] = 0xFFFFFFFF00000000ull;
        }
    }
}

// ---------------- phase 1: gates_x GEMM  C[m][p] = A[m][:] . Wp[p][:] + bias[p] ----------------
#define BM 128
#define BN 64
#define BK 16
#define LDA (BM + 4)
#define LDB (BN + 4)

__global__ __launch_bounds__(256) void gemm_x_kernel(const float* __restrict__ A) {
    __shared__ float sA[BK][LDA];
    __shared__ float sB[BK][LDB];
    int tid   = threadIdx.x;
    int mBase = blockIdx.y * BM;
    int nBase = blockIdx.x * BN;
    int tm = tid & 15, tn = tid >> 4;

    int aM0 = tid >> 2;
    int aK0 = (tid & 3) * 4;
    int bN  = tid >> 2;
    int bK  = (tid & 3) * 4;

    const float* Ag = A + (size_t)mBase * I_SZ;
    const float* Bg = g_wih_p + (size_t)nBase * I_SZ;

    float4 ra0 = *(const float4*)(Ag + (size_t)aM0 * I_SZ + aK0);
    float4 ra1 = *(const float4*)(Ag + (size_t)(aM0 + 64) * I_SZ + aK0);
    float4 rb  = *(const float4*)(Bg + (size_t)bN * I_SZ + bK);

    ull acc[4][4];
#pragma unroll
    for (int u = 0; u < 4; u++)
#pragma unroll
        for (int j = 0; j < 4; j++) acc[u][j] = 0ull;

    const int KT = I_SZ / BK;
    for (int kt = 0; kt < KT; kt++) {
        sA[aK0 + 0][aM0] = ra0.x; sA[aK0 + 1][aM0] = ra0.y;
        sA[aK0 + 2][aM0] = ra0.z; sA[aK0 + 3][aM0] = ra0.w;
        sA[aK0 + 0][aM0 + 64] = ra1.x; sA[aK0 + 1][aM0 + 64] = ra1.y;
        sA[aK0 + 2][aM0 + 64] = ra1.z; sA[aK0 + 3][aM0 + 64] = ra1.w;
        sB[bK + 0][bN] = rb.x; sB[bK + 1][bN] = rb.y;
        sB[bK + 2][bN] = rb.z; sB[bK + 3][bN] = rb.w;
        __syncthreads();

        if (kt + 1 < KT) {
            int k0 = (kt + 1) * BK;
            ra0 = *(const float4*)(Ag + (size_t)aM0 * I_SZ + k0 + aK0);
            ra1 = *(const float4*)(Ag + (size_t)(aM0 + 64) * I_SZ + k0 + aK0);
            rb  = *(const float4*)(Bg + (size_t)bN * I_SZ + k0 + bK);
        }

#pragma unroll
        for (int kk = 0; kk < BK; kk++) {
            ulonglong2 a01 = *(const ulonglong2*)&sA[kk][tm * 8];
            ulonglong2 a23 = *(const ulonglong2*)&sA[kk][tm * 8 + 4];
            float4 b4 = *(const float4*)&sB[kk][tn * 4];
            ull b0 = pack2(b4.x), b1 = pack2(b4.y), b2 = pack2(b4.z), b3 = pack2(b4.w);
            ffma2(acc[0][0], a01.x, b0); ffma2(acc[0][1], a01.x, b1);
            ffma2(acc[0][2], a01.x, b2); ffma2(acc[0][3], a01.x, b3);
            ffma2(acc[1][0], a01.y, b0); ffma2(acc[1][1], a01.y, b1);
            ffma2(acc[1][2], a01.y, b2); ffma2(acc[1][3], a01.y, b3);
            ffma2(acc[2][0], a23.x, b0); ffma2(acc[2][1], a23.x, b1);
            ffma2(acc[2][2], a23.x, b2); ffma2(acc[2][3], a23.x, b3);
            ffma2(acc[3][0], a23.y, b0); ffma2(acc[3][1], a23.y, b1);
            ffma2(acc[3][2], a23.y, b2); ffma2(acc[3][3], a23.y, b3);
        }
        __syncthreads();
    }

    float4 bias = *(const float4*)&g_bias_p[nBase + tn * 4];
    float* C = g_gates + (size_t)(mBase + tm * 8) * G4 + nBase + tn * 4;
#pragma unroll
    for (int u = 0; u < 4; u++) {
        float2 c0 = unpack2(acc[u][0]);
        float2 c1 = unpack2(acc[u][1]);
        float2 c2 = unpack2(acc[u][2]);
        float2 c3 = unpack2(acc[u][3]);
        float4 lo = {c0.x + bias.x, c1.x + bias.y, c2.x + bias.z, c3.x + bias.w};
        float4 hi = {c0.y + bias.x, c1.y + bias.y, c2.y + bias.z, c3.y + bias.w};
        *(float4*)(C + (size_t)(2 * u) * G4)     = lo;
        *(float4*)(C + (size_t)(2 * u + 1) * G4) = hi;
    }
}

// ---------------- phase 2: persistent scan, sync == tagged data ----------------
// 4 groups x 32 CTAs. Group grp owns batches [8g, 8g+8). CTA c owns packed rows
// [64c, 64c+64). h values travel as 64-bit (tag,t | h) words: producers publish
// with st.release.b64; consumers poll their own 16 words with ld.acquire.b64
// until tag == t. Point-to-point — no barrier, no atomics, no fences.
// Compute: thread tid = rq*8+b -> rows {rq, rq+32} x batch b, full K (no reduction).
__global__ __launch_bounds__(256) void scan_kernel(const float* __restrict__ c0,
                                                   float* __restrict__ out, int out_size) {
    extern __shared__ float smem[];
    float* sh_w = smem;                 // 64 x WPITCH
    float* sh_h = smem + 64 * WPITCH;   // 8 x WPITCH

    int tid  = threadIdx.x;
    int grp  = blockIdx.x >> 5;
    int c    = blockIdx.x & 31;
    int lane = tid & 31, wid = tid >> 5;
    int rq   = tid >> 3;                // 0..31
    int b    = tid & 7;

    // W_hh slice -> padded SMEM (resident all 1024 steps)
    {
        const float4* wsrc = (const float4*)(g_whh_p + (size_t)c * 64 * H_SZ);
#pragma unroll
        for (int i = 0; i < 32; i++) {
            int gi = tid + i * 256;          // float4 index 0..8191
            int rr = gi >> 7, k4 = gi & 127;
            *(float4*)(sh_w + rr * WPITCH + k4 * 4) = __ldg(wsrc + gi);
        }
    }

    ull* hpk = g_hpk + (size_t)grp * 2 * 8 * H_SZ;

    // epilogue role: lanes 0..15 per warp own (jl = wid or wid+8, b = lane&7)
    bool  epi = (lane < 16);
    int   eb  = lane & 7;
    int   ejl = wid + ((lane >> 3) & 1) * 8;   // 0..15
    int   ej  = c * 16 + ejl;
    int   ebg = grp * 8 + eb;
    float c_val = 0.f;
    const float4* gxp = (const float4*)g_gates;
    if (epi) {
        c_val = c0[(size_t)ebg * H_SZ + ej];
        gxp   = (const float4*)(g_gates + (size_t)ebg * G4 + c * 64 + ejl * 4);
    }
    __syncthreads();

    const float* wr0  = sh_w + rq * WPITCH;
    const float* wr1  = sh_w + (rq + 32) * WPITCH;
    const float* hrow = sh_h + b * WPITCH;

    for (int t = 0; t < T_STEPS; t++) {
        // prefetch gates_x (DRAM) — consumed ~2K cycles later in the epilogue
        float4 gxv = make_float4(0.f, 0.f, 0.f, 0.f);
        if (epi) gxv = __ldg(gxp + (size_t)t * (B_SZ * G4 / 4));

        // poll + stage this thread's 16 h-words (tag must equal t). First pass
        // issues all 16 acquires with full MLP; spins only on stragglers.
        {
            const ull* hb = hpk + (t & 1) * (8 * H_SZ);
            ull v[16];
#pragma unroll
            for (int i = 0; i < 16; i++) v[i] = ld_acq64(hb + tid + i * 256);
#pragma unroll
            for (int i = 0; i < 16; i++) {
                while ((unsigned)(v[i] >> 32) != (unsigned)t)
                    v[i] = ld_acq64(hb + tid + i * 256);
                int w = tid + i * 256;
                sh_h[(w >> 9) * WPITCH + (w & 511)] = __uint_as_float((unsigned)v[i]);
            }
        }
        __syncthreads();

        // dot: rows {rq, rq+32} x batch b over K=512
        ull a0 = 0, a1 = 0, a2 = 0, a3 = 0;
#pragma unroll 8
        for (int k = 0; k < H_SZ; k += 4) {
            ulonglong2 hh = *(const ulonglong2*)(hrow + k);
            ulonglong2 w0 = *(const ulonglong2*)(wr0 + k);
            ulonglong2 w1 = *(const ulonglong2*)(wr1 + k);
            ffma2(a0, hh.x, w0.x); ffma2(a1, hh.y, w0.y);
            ffma2(a2, hh.x, w1.x); ffma2(a3, hh.y, w1.y);
        }
        fadd2(a0, a1); fadd2(a2, a3);
        float2 s1f = unpack2(a0), s2f = unpack2(a2);
        float s1 = s1f.x + s1f.y;     // row rq      (jl = wid,   gate = lane>>3)
        float s2 = s2f.x + s2f.y;     // row rq + 32 (jl = wid+8)
        ull sv; asm("mov.b64 %0, {%1, %2};" : "=l"(sv) : "f"(s1), "f"(s2));

        int bl = lane & 7;
        ull q0 = __shfl_sync(0xffffffffu, sv, bl);
        ull q1 = __shfl_sync(0xffffffffu, sv, bl + 8);
        ull q2 = __shfl_sync(0xffffffffu, sv, bl + 16);
        ull q3 = __shfl_sync(0xffffffffu, sv, bl + 24);

        if (epi) {
            bool lo = (lane < 8);
            float2 G0 = unpack2(q0), G1 = unpack2(q1), G2 = unpack2(q2), G3 = unpack2(q3);
            float pi = (lo ? G0.x : G0.y) + gxv.x;
            float pf = (lo ? G1.x : G1.y) + gxv.y;
            float pg = (lo ? G2.x : G2.y) + gxv.z;
            float po = (lo ? G3.x : G3.y) + gxv.w;
            float ig = sigf(pi), fg = sigf(pf), og = sigf(po);
            float gg = tanh_fast(pg);
            c_val = fg * c_val + ig * gg;
            float hn = og * tanh_fast(c_val);
            // publish immediately: data + tag in one release store
            ull pk = (ull)__float_as_uint(hn) | ((ull)(unsigned)(t + 1) << 32);
            st_rel64(hpk + ((t + 1) & 1) * (8 * H_SZ) + eb * H_SZ + ej, pk);
            out[(size_t)t * BH + (size_t)ebg * H_SZ + ej] = hn;
            if (t == T_STEPS - 1 && out_size >= TBH + 2 * BH) {
                out[TBH + ebg * H_SZ + ej]      = hn;     // h_f
                out[TBH + BH + ebg * H_SZ + ej] = c_val;  // c_f
            }
        }
        __syncthreads();                  // sh_h reads done before next stage
    }
}

// ---------------- launch ----------------
extern "C" void kernel_launch(void* const* d_in, const int* in_sizes, int n_in,
                              void* d_out, int out_size) {
    const float* input = (const float*)d_in[0];
    const float* h0    = (const float*)d_in[1];
    const float* c0    = (const float*)d_in[2];
    const float* Wih   = (const float*)d_in[3];
    const float* Whh   = (const float*)d_in[4];
    const float* bih   = (const float*)d_in[5];
    const float* bhh   = (const float*)d_in[6];
    float* out = (float*)d_out;

    prep_kernel<<<G4, 128>>>(Wih, Whh, bih, bhh, h0);

    dim3 grid(G4 / BN, (T_STEPS * B_SZ) / BM);
    gemm_x_kernel<<<grid, 256>>>(input);

    const int scan_smem = 72 * WPITCH * (int)sizeof(float);  // 148608 B
    cudaFuncSetAttribute(scan_kernel, cudaFuncAttributeMaxDynamicSharedMemorySize, scan_smem);
    scan_kernel<<<NG * NC, 256, scan_smem>>>(c0, out, out_size);
}

// round 7
// speedup vs baseline: 1.4223x; 1.3090x over previous
#include <cuda_runtime.h>
#include <cstdint>

#define T_STEPS 1024
#define B_SZ    32
#define I_SZ    512
#define H_SZ    512
#define G4      2048                 // 4*H
#define TBH     (T_STEPS * B_SZ * H_SZ)
#define BH      (B_SZ * H_SZ)
#define NG      4                    // independent batch groups (8 batches each)
#define NC      32                   // CTAs per group
#define WPITCH  516                  // padded smem row pitch (floats)
#define RING    16                   // out-ring depth (steps)

typedef unsigned long long ull;

// ---------------- device scratch (no allocation allowed) ----------------
__device__ float g_gates[(size_t)T_STEPS * B_SZ * G4];   // [t][b][p], p = 4j+g
__device__ float g_wih_p[G4 * I_SZ];                     // packed W_ih (p = 4j+g)
__device__ float g_whh_p[G4 * H_SZ];                     // packed W_hh (p = 4j+g)
__device__ float g_bias_p[G4];                           // b_ih + b_hh, packed
__device__ float g_hbuf[NG * 2 * 8 * H_SZ];              // [grp][ph][b8][j]
__device__ unsigned g_cnt[NG * 32];                      // per-group arrival counter (padded)
__device__ unsigned g_gen[NG * 32];                      // per-group generation (padded)

// ---------------- packed f32x2 helpers ----------------
__device__ __forceinline__ void ffma2(ull &d, ull a, ull b) {
    asm("fma.rn.f32x2 %0, %1, %2, %3;" : "=l"(d) : "l"(a), "l"(b), "l"(d));
}
__device__ __forceinline__ void fadd2(ull &d, ull a) {
    asm("add.rn.f32x2 %0, %1, %2;" : "=l"(d) : "l"(d), "l"(a));
}
__device__ __forceinline__ ull pack2(float x) {
    ull r; asm("mov.b64 %0, {%1, %1};" : "=l"(r) : "f"(x)); return r;
}
__device__ __forceinline__ float2 unpack2(ull v) {
    float2 r; asm("mov.b64 {%0, %1}, %2;" : "=f"(r.x), "=f"(r.y) : "l"(v)); return r;
}
__device__ __forceinline__ unsigned ld_acq(const unsigned* p) {
    unsigned v; asm volatile("ld.acquire.gpu.global.u32 %0, [%1];" : "=r"(v) : "l"(p) : "memory");
    return v;
}
__device__ __forceinline__ void st_rel(unsigned* p, unsigned v) {
    asm volatile("st.release.gpu.global.u32 [%0], %1;" :: "l"(p), "r"(v) : "memory");
}

__device__ __forceinline__ float sigf(float x) {
    return __fdividef(1.f, 1.f + __expf(-x));
}
__device__ __forceinline__ float tanh_fast(float x) {
    float ax = fabsf(x);
    float e  = __expf(-2.f * ax);
    float r  = __fdividef(1.f - e, 1.f + e);
    return copysignf(r, x);
}

// ---------------- prep: pack weights, scatter h0, reset sync words ----------------
__global__ void prep_kernel(const float* __restrict__ Wih, const float* __restrict__ Whh,
                            const float* __restrict__ bih, const float* __restrict__ bhh,
                            const float* __restrict__ h0) {
    int p = blockIdx.x;                     // packed row p = 4j + g
    int g = p & 3, j = p >> 2;
    int orig = g * H_SZ + j;

    const float* srcI = Wih + (size_t)orig * I_SZ;
    const float* srcH = Whh + (size_t)orig * H_SZ;
    float* dI = g_wih_p + (size_t)p * I_SZ;
    float* dH = g_whh_p + (size_t)p * H_SZ;
    for (int k = threadIdx.x; k < I_SZ; k += blockDim.x) dI[k] = srcI[k];
    for (int k = threadIdx.x; k < H_SZ; k += blockDim.x) dH[k] = srcH[k];
    if (threadIdx.x == 0) g_bias_p[p] = bih[orig] + bhh[orig];

    if (p < H_SZ) {                          // h0 -> g_hbuf[grp][0][b&7][j=p]
        for (int b = threadIdx.x; b < B_SZ; b += blockDim.x)
            g_hbuf[((size_t)(b >> 3) * 2 * 8 + (b & 7)) * H_SZ + p] = h0[(size_t)b * H_SZ + p];
    }
    if (p < NG && threadIdx.x == 0) { g_cnt[p * 32] = 0; g_gen[p * 32] = 0; }
}

// ---------------- phase 1: gates_x GEMM  C[m][p] = A[m][:] . Wp[p][:] + bias[p] ----------------
#define BM 128
#define BN 64
#define BK 16
#define LDA (BM + 4)
#define LDB (BN + 4)

__global__ __launch_bounds__(256) void gemm_x_kernel(const float* __restrict__ A) {
    __shared__ float sA[BK][LDA];
    __shared__ float sB[BK][LDB];
    int tid   = threadIdx.x;
    int mBase = blockIdx.y * BM;
    int nBase = blockIdx.x * BN;
    int tm = tid & 15, tn = tid >> 4;

    int aM0 = tid >> 2;
    int aK0 = (tid & 3) * 4;
    int bN  = tid >> 2;
    int bK  = (tid & 3) * 4;

    const float* Ag = A + (size_t)mBase * I_SZ;
    const float* Bg = g_wih_p + (size_t)nBase * I_SZ;

    float4 ra0 = *(const float4*)(Ag + (size_t)aM0 * I_SZ + aK0);
    float4 ra1 = *(const float4*)(Ag + (size_t)(aM0 + 64) * I_SZ + aK0);
    float4 rb  = *(const float4*)(Bg + (size_t)bN * I_SZ + bK);

    ull acc[4][4];
#pragma unroll
    for (int u = 0; u < 4; u++)
#pragma unroll
        for (int j = 0; j < 4; j++) acc[u][j] = 0ull;

    const int KT = I_SZ / BK;
    for (int kt = 0; kt < KT; kt++) {
        sA[aK0 + 0][aM0] = ra0.x; sA[aK0 + 1][aM0] = ra0.y;
        sA[aK0 + 2][aM0] = ra0.z; sA[aK0 + 3][aM0] = ra0.w;
        sA[aK0 + 0][aM0 + 64] = ra1.x; sA[aK0 + 1][aM0 + 64] = ra1.y;
        sA[aK0 + 2][aM0 + 64] = ra1.z; sA[aK0 + 3][aM0 + 64] = ra1.w;
        sB[bK + 0][bN] = rb.x; sB[bK + 1][bN] = rb.y;
        sB[bK + 2][bN] = rb.z; sB[bK + 3][bN] = rb.w;
        __syncthreads();

        if (kt + 1 < KT) {
            int k0 = (kt + 1) * BK;
            ra0 = *(const float4*)(Ag + (size_t)aM0 * I_SZ + k0 + aK0);
            ra1 = *(const float4*)(Ag + (size_t)(aM0 + 64) * I_SZ + k0 + aK0);
            rb  = *(const float4*)(Bg + (size_t)bN * I_SZ + k0 + bK);
        }

#pragma unroll
        for (int kk = 0; kk < BK; kk++) {
            ulonglong2 a01 = *(const ulonglong2*)&sA[kk][tm * 8];
            ulonglong2 a23 = *(const ulonglong2*)&sA[kk][tm * 8 + 4];
            float4 b4 = *(const float4*)&sB[kk][tn * 4];
            ull b0 = pack2(b4.x), b1 = pack2(b4.y), b2 = pack2(b4.z), b3 = pack2(b4.w);
            ffma2(acc[0][0], a01.x, b0); ffma2(acc[0][1], a01.x, b1);
            ffma2(acc[0][2], a01.x, b2); ffma2(acc[0][3], a01.x, b3);
            ffma2(acc[1][0], a01.y, b0); ffma2(acc[1][1], a01.y, b1);
            ffma2(acc[1][2], a01.y, b2); ffma2(acc[1][3], a01.y, b3);
            ffma2(acc[2][0], a23.x, b0); ffma2(acc[2][1], a23.x, b1);
            ffma2(acc[2][2], a23.x, b2); ffma2(acc[2][3], a23.x, b3);
            ffma2(acc[3][0], a23.y, b0); ffma2(acc[3][1], a23.y, b1);
            ffma2(acc[3][2], a23.y, b2); ffma2(acc[3][3], a23.y, b3);
        }
        __syncthreads();
    }

    float4 bias = *(const float4*)&g_bias_p[nBase + tn * 4];
    float* C = g_gates + (size_t)(mBase + tm * 8) * G4 + nBase + tn * 4;
#pragma unroll
    for (int u = 0; u < 4; u++) {
        float2 c0 = unpack2(acc[u][0]);
        float2 c1 = unpack2(acc[u][1]);
        float2 c2 = unpack2(acc[u][2]);
        float2 c3 = unpack2(acc[u][3]);
        float4 lo = {c0.x + bias.x, c1.x + bias.y, c2.x + bias.z, c3.x + bias.w};
        float4 hi = {c0.y + bias.x, c1.y + bias.y, c2.y + bias.z, c3.y + bias.w};
        *(float4*)(C + (size_t)(2 * u) * G4)     = lo;
        *(float4*)(C + (size_t)(2 * u + 1) * G4) = hi;
    }
}

// ---------------- phase 2: persistent scan (R2 sync + R6 compute + deferred out) -------
// 4 groups x 32 CTAs. Group grp owns batches [8g, 8g+8). CTA c owns packed rows
// [64c, 64c+64). Sync: per-group atomicAdd counter + single gen word (release store),
// polled by tid0 only. Compute: thread tid = rq*8+b -> rows {rq, rq+32} x batch b,
// full K, zero reduction; gates gathered by warp shuffle. out[] values are stashed in
// an smem ring and flushed coalesced every 16 steps AFTER the arrival point, so the
// per-step publish fence covers only the 512B h store.
__global__ __launch_bounds__(256) void scan_kernel(const float* __restrict__ c0,
                                                   float* __restrict__ out, int out_size) {
    extern __shared__ float smem[];
    float* sh_w   = smem;                        // 64 x WPITCH
    float* sh_h   = smem + 64 * WPITCH;          // 8 x WPITCH
    float* sring  = smem + 72 * WPITCH;          // RING x 128 out-ring

    int tid  = threadIdx.x;
    int grp  = blockIdx.x >> 5;
    int c    = blockIdx.x & 31;
    int lane = tid & 31, wid = tid >> 5;
    int rq   = tid >> 3;                // 0..31
    int b    = tid & 7;

    // W_hh slice -> padded SMEM (resident all 1024 steps)
    {
        const float4* wsrc = (const float4*)(g_whh_p + (size_t)c * 64 * H_SZ);
#pragma unroll
        for (int i = 0; i < 32; i++) {
            int gi = tid + i * 256;          // float4 index 0..8191
            int rr = gi >> 7, k4 = gi & 127;
            *(float4*)(sh_w + rr * WPITCH + k4 * 4) = __ldg(wsrc + gi);
        }
    }

    unsigned* cnt = g_cnt + grp * 32;
    unsigned* gen = g_gen + grp * 32;
    float* hglob  = g_hbuf + (size_t)grp * 2 * 8 * H_SZ;

    // epilogue role: lanes 0..15 per warp own (jl = wid or wid+8, b = lane&7)
    bool  epi = (lane < 16);
    int   eb  = lane & 7;
    int   ejl = wid + ((lane >> 3) & 1) * 8;   // 0..15
    int   ej  = c * 16 + ejl;
    int   ebg = grp * 8 + eb;
    float c_val = 0.f;
    const float4* gxp = (const float4*)g_gates;
    if (epi) {
        c_val = c0[(size_t)ebg * H_SZ + ej];
        gxp   = (const float4*)(g_gates + (size_t)ebg * G4 + c * 64 + ejl * 4);
    }
    __syncthreads();

    const float* wr0  = sh_w + rq * WPITCH;
    const float* wr1  = sh_w + (rq + 32) * WPITCH;
    const float* hrow = sh_h + b * WPITCH;

    for (int t = 0; t < T_STEPS; t++) {
        // prefetch gates_x (DRAM) — consumed ~2.5K cycles later
        float4 gxv = make_float4(0.f, 0.f, 0.f, 0.f);
        if (epi) gxv = __ldg(gxp + (size_t)t * (B_SZ * G4 / 4));

        // wait for h[t]: tid0 polls the single gen word
        if (tid == 0) {
            while (ld_acq(gen) < (unsigned)t) {}
        }
        __syncthreads();

        // stage h[t] -> padded SMEM (16KB, L2-coherent)
        {
            const float4* hsrc = (const float4*)(hglob + (t & 1) * (8 * H_SZ));
#pragma unroll
            for (int i = 0; i < 4; i++) {
                int gi = tid + i * 256;      // float4 index 0..1023
                int hb = gi >> 7, k4 = gi & 127;
                *(float4*)(sh_h + hb * WPITCH + k4 * 4) = __ldcg(hsrc + gi);
            }
        }
        __syncthreads();

        // dot: rows {rq, rq+32} x batch b over K=512
        ull a0 = 0, a1 = 0, a2 = 0, a3 = 0;
#pragma unroll 8
        for (int k = 0; k < H_SZ; k += 4) {
            ulonglong2 hh = *(const ulonglong2*)(hrow + k);
            ulonglong2 w0 = *(const ulonglong2*)(wr0 + k);
            ulonglong2 w1 = *(const ulonglong2*)(wr1 + k);
            ffma2(a0, hh.x, w0.x); ffma2(a1, hh.y, w0.y);
            ffma2(a2, hh.x, w1.x); ffma2(a3, hh.y, w1.y);
        }
        fadd2(a0, a1); fadd2(a2, a3);
        float2 s1f = unpack2(a0), s2f = unpack2(a2);
        float s1 = s1f.x + s1f.y;     // row rq      (jl = wid)
        float s2 = s2f.x + s2f.y;     // row rq + 32 (jl = wid+8)
        ull sv; asm("mov.b64 %0, {%1, %2};" : "=l"(sv) : "f"(s1), "f"(s2));

        int bl = lane & 7;
        ull q0 = __shfl_sync(0xffffffffu, sv, bl);
        ull q1 = __shfl_sync(0xffffffffu, sv, bl + 8);
        ull q2 = __shfl_sync(0xffffffffu, sv, bl + 16);
        ull q3 = __shfl_sync(0xffffffffu, sv, bl + 24);

        if (epi) {
            bool lo = (lane < 8);
            float2 G0 = unpack2(q0), G1 = unpack2(q1), G2 = unpack2(q2), G3 = unpack2(q3);
            float pi = (lo ? G0.x : G0.y) + gxv.x;
            float pf = (lo ? G1.x : G1.y) + gxv.y;
            float pg = (lo ? G2.x : G2.y) + gxv.z;
            float po = (lo ? G3.x : G3.y) + gxv.w;
            float ig = sigf(pi), fg = sigf(pf), og = sigf(po);
            float gg = tanh_fast(pg);
            c_val = fg * c_val + ig * gg;
            float hn = og * tanh_fast(c_val);
            hglob[((t + 1) & 1) * (8 * H_SZ) + eb * H_SZ + ej] = hn;   // publish h
            sring[(t & (RING - 1)) * 128 + eb * 16 + ejl] = hn;        // stash out
            if (t == T_STEPS - 1 && out_size >= TBH + 2 * BH) {
                out[TBH + ebg * H_SZ + ej]      = hn;     // h_f
                out[TBH + BH + ebg * H_SZ + ej] = c_val;  // c_f
            }
        }

        __syncthreads();                      // h stores visible CTA-wide
        if (tid == 0) {
            __threadfence();                  // only the 512B h publish pending
            unsigned old = atomicAdd(cnt, 1u);
            if (old == (unsigned)(t + 1) * NC - 1u)
                st_rel(gen, (unsigned)(t + 1));
        }

        // coalesced out flush (off the critical path, every RING steps)
        if ((t & (RING - 1)) == RING - 1) {
            int t0 = t - (RING - 1);
            int pair = tid >> 1;              // 0..127 = (s, eb)
            int s  = pair >> 3;
            int fb = pair & 7;
            int j0 = (tid & 1) * 8;
            const float* src = sring + s * 128 + fb * 16 + j0;
            float* dst = out + (size_t)(t0 + s) * BH + (size_t)(grp * 8 + fb) * H_SZ
                             + c * 16 + j0;
#pragma unroll
            for (int q = 0; q < 8; q++) dst[q] = src[q];
        }
    }
}

// ---------------- launch ----------------
extern "C" void kernel_launch(void* const* d_in, const int* in_sizes, int n_in,
                              void* d_out, int out_size) {
    const float* input = (const float*)d_in[0];
    const float* h0    = (const float*)d_in[1];
    const float* c0    = (const float*)d_in[2];
    const float* Wih   = (const float*)d_in[3];
    const float* Whh   = (const float*)d_in[4];
    const float* bih   = (const float*)d_in[5];
    const float* bhh   = (const float*)d_in[6];
    float* out = (float*)d_out;

    prep_kernel<<<G4, 128>>>(Wih, Whh, bih, bhh, h0);

    dim3 grid(G4 / BN, (T_STEPS * B_SZ) / BM);
    gemm_x_kernel<<<grid, 256>>>(input);

    const int scan_smem = (72 * WPITCH + RING * 128) * (int)sizeof(float);  // 156800 B
    cudaFuncSetAttribute(scan_kernel, cudaFuncAttributeMaxDynamicSharedMemorySize, scan_smem);
    scan_kernel<<<NG * NC, 256, scan_smem>>>(c0, out, out_size);
}